// round 11
// baseline (speedup 1.0000x reference)
#include <cuda_runtime.h>
#include <cuda_fp16.h>
#include <cuda_bf16.h>
#include <cstdint>

// ---------------- problem constants ----------------
#define NQ      1024      // 64 batches * 16 slots
#define MCW     16001     // codebook rows
#define MPAD    16128     // 126 * 128
#define KDIM    2016
#define BM      64
#define BN      128
#define BK      32
#define NKITER  63        // 2016 / 32
#define SEGLEN  3         // k-iters per accumulation segment (63 = 21*3)
#define NSTAGE  3

// dtype codes
#define DT_F16  0
#define DT_BF16 1
#define DT_F32  2

// ---------------- scratch (static device memory; no allocs) ----------------
__device__ int    g_dt_x;                    // dtype of x
__device__ int    g_dt_d;                    // dtype of data
__device__ __half g_xq[NQ * KDIM];           // permuted queries, k-major
__device__ __half g_cb[(size_t)MPAD * KDIM]; // codebook fp16 (rows >= MCW stay zero)
__device__ float  g_xs[NQ];                  // sum x
__device__ float  g_x2[NQ];                  // sum x^2
__device__ float  g_c2[MPAD];                // sum c^2
__device__ float  g_cn2[MPAD];               // sum (1-c)^2
__device__ float  g_xc[(size_t)NQ * MPAD];   // GEMM output (66 MB)

// ---------------- small PTX helpers ----------------
__device__ __forceinline__ uint32_t smem_u32(const void* p) {
    uint32_t a;
    asm("{ .reg .u64 t; cvta.to.shared.u64 t, %1; cvt.u32.u64 %0, t; }" : "=r"(a) : "l"(p));
    return a;
}
__device__ __forceinline__ void cp16(uint32_t dst, const void* src) {
    asm volatile("cp.async.cg.shared.global [%0], [%1], 16;\n" :: "r"(dst), "l"(src));
}
__device__ __forceinline__ void cp_commit() { asm volatile("cp.async.commit_group;\n"); }
__device__ __forceinline__ void ldsm4(uint32_t* r, uint32_t addr) {
    asm volatile("ldmatrix.sync.aligned.m8n8.x4.shared.b16 {%0,%1,%2,%3}, [%4];"
                 : "=r"(r[0]), "=r"(r[1]), "=r"(r[2]), "=r"(r[3]) : "r"(addr));
}
__device__ __forceinline__ void mma16816(float* d, const uint32_t* a, uint32_t b0, uint32_t b1) {
    asm volatile("mma.sync.aligned.m16n8k16.row.col.f32.f16.f16.f32 "
                 "{%0,%1,%2,%3}, {%4,%5,%6,%7}, {%8,%9}, {%0,%1,%2,%3};\n"
                 : "+f"(d[0]), "+f"(d[1]), "+f"(d[2]), "+f"(d[3])
                 : "r"(a[0]), "r"(a[1]), "r"(a[2]), "r"(a[3]), "r"(b0), "r"(b1));
}

// ---------------- generic 8-element load ----------------
__device__ __forceinline__ void load8(const void* p, size_t off, int dt, float* f) {
    if (dt == DT_F32) {
        const float4* q = (const float4*)((const float*)p + off);
        float4 v0 = q[0], v1 = q[1];
        f[0]=v0.x; f[1]=v0.y; f[2]=v0.z; f[3]=v0.w;
        f[4]=v1.x; f[5]=v1.y; f[6]=v1.z; f[7]=v1.w;
    } else if (dt == DT_F16) {
        uint4 v = *(const uint4*)((const __half*)p + off);
        const __half2* hp = (const __half2*)&v;
#pragma unroll
        for (int i = 0; i < 4; i++) {
            float2 g = __half22float2(hp[i]);
            f[2*i] = g.x; f[2*i+1] = g.y;
        }
    } else {
        uint4 v = *(const uint4*)((const __nv_bfloat16*)p + off);
        const __nv_bfloat162* hp = (const __nv_bfloat162*)&v;
#pragma unroll
        for (int i = 0; i < 4; i++) {
            float2 g = __bfloat1622float2(hp[i]);
            f[2*i] = g.x; f[2*i+1] = g.y;
        }
    }
}

// ---------------- kernel 0: dtype detection ----------------
__global__ void detect_kernel(const uint32_t* x, const uint32_t* d) {
    const uint32_t* ps[2] = {x, d};
    int* outs[2] = {&g_dt_x, &g_dt_d};
    for (int a = 0; a < 2; a++) {
        uint32_t lowmax = 0, highmax = 0;
        for (int i = 0; i < 64; i++) {
            uint32_t w = ps[a][i];
            uint32_t lo = w & 0xFFFFu, hi = w >> 16;
            if (lo > lowmax) lowmax = lo;
            if (hi > highmax) highmax = hi;
        }
        int dt;
        if (lowmax >= 0x4000u)       dt = DT_F32;
        else if (highmax >= 0x3C00u) dt = DT_BF16;
        else                         dt = DT_F16;
        *outs[a] = dt;
    }
}

// ---------------- kernel 1: permute x -> xq (fp16), compute xs/x2 ----------------
__global__ __launch_bounds__(256) void build_xq_kernel(const void* xraw) {
    const int q = blockIdx.x;
    const int b = q >> 4, slot = q & 15;
    const int t = threadIdx.x;
    const int dt = g_dt_x;
    float s = 0.f, s2 = 0.f;
    if (t < 252) {
        const int ch = t / 126, row = t % 126;
        const size_t off = (size_t)b * 32256 + ch * 16128 + row * 128 + slot * 8;
        float f[8];
        load8(xraw, off, dt, f);
        __half h[8];
#pragma unroll
        for (int i = 0; i < 8; i++) {
            h[i] = __float2half_rn(f[i]);
            s  += f[i];
            s2 += f[i] * f[i];
        }
        *(uint4*)(g_xq + (size_t)q * KDIM + t * 8) = *(const uint4*)h;
    }
    __shared__ float r0[256], r1[256];
    r0[t] = s; r1[t] = s2; __syncthreads();
    for (int st = 128; st > 0; st >>= 1) {
        if (t < st) { r0[t] += r0[t + st]; r1[t] += r1[t + st]; }
        __syncthreads();
    }
    if (t == 0) { g_xs[q] = r0[0]; g_x2[q] = r1[0]; }
}

// ---------------- kernel 2: codebook -> fp16 + per-row c2/cn2 ----------------
__global__ __launch_bounds__(128) void prep_cb_kernel(const void* draw) {
    const int m = blockIdx.x;
    const int t = threadIdx.x;
    const int dt = g_dt_d;
    __half* dst = g_cb + (size_t)m * KDIM;
    float s2 = 0.f, sn2 = 0.f;
    for (int v = t; v < 252; v += 128) {
        float f[8];
        load8(draw, (size_t)m * KDIM + v * 8, dt, f);
        __half h[8];
#pragma unroll
        for (int i = 0; i < 8; i++) {
            h[i] = __float2half_rn(f[i]);
            s2 += f[i] * f[i];
            float g1 = 1.0f - f[i];
            sn2 += g1 * g1;
        }
        *(uint4*)(dst + v * 8) = *(const uint4*)h;
    }
    __shared__ float r0[128], r1[128];
    r0[t] = s2; r1[t] = sn2; __syncthreads();
    for (int st = 64; st > 0; st >>= 1) {
        if (t < st) { r0[t] += r0[t + st]; r1[t] += r1[t + st]; }
        __syncthreads();
    }
    if (t == 0) { g_c2[m] = r0[0]; g_cn2[m] = r1[0]; }
}

// ---------------- kernel 3: GEMM xc = xq * cb^T, high-accuracy accumulation --------
// CTA tile 64(q) x 128(m), 512 threads / 16 warps (warp tile 16x32), 3-stage
// cp.async pipeline. RACE FIX vs R7: the final iteration must wait_group 0 --
// at kt=62 only stage 62's group is in flight, so wait_group 1 waited for
// nothing and the last K-chunk ldsm raced the in-flight cp.async (caused the
// post-timing nondeterminism). Numerics identical to the R6 pass.
#define APITCH 40
#define A_STAGE (BM * APITCH)            // halfs
#define B_STAGE (BN * APITCH)
#define A_STAGE_BYTES (A_STAGE * 2)
#define B_STAGE_BYTES (B_STAGE * 2)

__global__ __launch_bounds__(512) void gemm_kernel() {
    __shared__ __half sA[NSTAGE][A_STAGE];
    __shared__ __half sB[NSTAGE][B_STAGE];

    const int tile_n = blockIdx.x * BN;
    const int tile_m = blockIdx.y * BM;
    const int tid  = threadIdx.x;
    const int wid  = tid >> 5;
    const int lane = tid & 31;
    const int warp_q = wid & 3;    // 4 q-tiles of 16
    const int warp_n = wid >> 2;   // 4 n-tiles of 32

    const uint32_t sA_u = smem_u32(&sA[0][0]);
    const uint32_t sB_u = smem_u32(&sB[0][0]);

    const int rowA = tid >> 2;            // 0..127
    const int ka   = (tid & 3) * 8;
    const __half* gA = g_xq + (size_t)(tile_m + rowA) * KDIM + ka;   // deref'd only for tid<256
    const __half* gB = g_cb + (size_t)(tile_n + rowA) * KDIM + ka;

    const uint32_t dA = sA_u + ((rowA * APITCH + ka) << 1);
    const uint32_t dB = sB_u + ((rowA * APITCH + ka) << 1);

    float sum[4][4], comp[4][4], chunk[4][4];
#pragma unroll
    for (int j = 0; j < 4; j++)
#pragma unroll
        for (int k = 0; k < 4; k++) { sum[j][k] = 0.f; comp[j][k] = 0.f; chunk[j][k] = 0.f; }

    const int arow  = warp_q * 16 + (lane & 15);
    const int akoff = (lane >> 4) << 3;
    const int bn    = warp_n * 32 + (lane & 7) + ((lane >> 4) << 3);
    const int bkoff = lane & 8;

    // prologue: stages 0 and 1
#pragma unroll
    for (int s = 0; s < NSTAGE - 1; s++) {
        const int k0 = s * BK;
        if (tid < 256) cp16(dA + s * A_STAGE_BYTES, gA + k0);
        cp16(dB + s * B_STAGE_BYTES, gB + k0);
        cp_commit();
    }

    for (int kt = 0; kt < NKITER; kt++) {
        // Tail-correct wait: at kt = NKITER-1 only the current stage's group
        // remains in flight, so we must drain ALL groups.
        if (kt + 1 < NKITER) {
            asm volatile("cp.async.wait_group 1;\n");
        } else {
            asm volatile("cp.async.wait_group 0;\n");
        }
        __syncthreads();

        const int buf = kt % NSTAGE;
        const uint32_t aB = sA_u + buf * A_STAGE_BYTES;
        const uint32_t bB = sB_u + buf * B_STAGE_BYTES;
#pragma unroll
        for (int ks = 0; ks < 2; ks++) {
            const int kh = ks * 16;
            uint32_t ra[4], rb[2][4];
            ldsm4(ra, aB + ((arow * APITCH + kh + akoff) << 1));
            uint32_t b0 = bB + ((bn * APITCH + kh + bkoff) << 1);
            ldsm4(rb[0], b0);
            ldsm4(rb[1], b0 + (16 * APITCH << 1));
#pragma unroll
            for (int nt = 0; nt < 4; nt++)
                mma16816(chunk[nt], ra,
                         rb[nt >> 1][(nt & 1) * 2], rb[nt >> 1][(nt & 1) * 2 + 1]);
        }

        // end of segment: Kahan-fold chunk into (sum, comp), reset chunk
        if ((kt % SEGLEN) == (SEGLEN - 1)) {
#pragma unroll
            for (int nt = 0; nt < 4; nt++)
#pragma unroll
                for (int e = 0; e < 4; e++) {
                    float y = __fsub_rn(chunk[nt][e], comp[nt][e]);
                    float tt = __fadd_rn(sum[nt][e], y);
                    comp[nt][e] = __fsub_rn(__fsub_rn(tt, sum[nt][e]), y);
                    sum[nt][e] = tt;
                    chunk[nt][e] = 0.f;
                }
        }
        __syncthreads();

        // issue load for stage kt + NSTAGE - 1 into the slot just freed
        const int knext = kt + NSTAGE - 1;
        if (knext < NKITER) {
            const int nbuf = knext % NSTAGE;
            const int k0 = knext * BK;
            if (tid < 256) cp16(dA + nbuf * A_STAGE_BYTES, gA + k0);
            cp16(dB + nbuf * B_STAGE_BYTES, gB + k0);
            cp_commit();
        }
    }

    // epilogue: xc = sum + comp
#pragma unroll
    for (int nt = 0; nt < 4; nt++) {
        const int r = tile_m + warp_q * 16 + (lane >> 2);
        const int c = tile_n + warp_n * 32 + nt * 8 + (lane & 3) * 2;
        float2 v0 = make_float2(__fadd_rn(sum[nt][0], comp[nt][0]),
                                __fadd_rn(sum[nt][1], comp[nt][1]));
        float2 v1 = make_float2(__fadd_rn(sum[nt][2], comp[nt][2]),
                                __fadd_rn(sum[nt][3], comp[nt][3]));
        *(float2*)&g_xc[(size_t)r * MPAD + c] = v0;
        *(float2*)&g_xc[(size_t)(r + 8) * MPAD + c] = v1;
    }
}

// ---------------- kernel 4: fused distance + argmin + bit expansion ----------------
__device__ __forceinline__ void blockReduceMinIdx(float& v, int& i, float* sv, int* si) {
    const int t = threadIdx.x;
    sv[t] = v; si[t] = i; __syncthreads();
    for (int s = 128; s > 0; s >>= 1) {
        if (t < s) {
            float ov = sv[t + s]; int oi = si[t + s];
            if (ov < sv[t] || (ov == sv[t] && oi < si[t])) { sv[t] = ov; si[t] = oi; }
        }
        __syncthreads();
    }
    v = sv[0]; i = si[0];
    __syncthreads();
}

__global__ __launch_bounds__(256) void argmin_kernel(float* __restrict__ out) {
    const int q0 = blockIdx.x * 4;
    const int t = threadIdx.x;
    float bv0[4], bv1[4];
    int bi0[4], bi1[4];
    float x2[4], xs[4];
#pragma unroll
    for (int j = 0; j < 4; j++) {
        bv0[j] = 3.4e38f; bv1[j] = 3.4e38f; bi0[j] = 0; bi1[j] = 0;
        x2[j] = g_x2[q0 + j]; xs[j] = g_xs[q0 + j];
    }
    for (int m = t; m < MCW; m += 256) {
        const float c2 = g_c2[m];
        const float cn2 = g_cn2[m];
#pragma unroll
        for (int j = 0; j < 4; j++) {
            const float xc = g_xc[(size_t)(q0 + j) * MPAD + m];
            const float d0 = __fsub_rn(__fadd_rn(x2[j], c2), 2.0f * xc);
            const float d1 = __fsub_rn(__fadd_rn(x2[j], cn2), 2.0f * __fsub_rn(xs[j], xc));
            if (d0 < bv0[j]) { bv0[j] = d0; bi0[j] = m; }
            if (d1 < bv1[j]) { bv1[j] = d1; bi1[j] = m; }
        }
    }
    __shared__ float sv[256];
    __shared__ int si[256];
    __shared__ int result[4];
#pragma unroll
    for (int j = 0; j < 4; j++) {
        float v0 = bv0[j]; int i0 = bi0[j];
        blockReduceMinIdx(v0, i0, sv, si);
        float v1 = bv1[j]; int i1 = bi1[j];
        blockReduceMinIdx(v1, i1, sv, si);
        if (t == 0) {
            // [d0, d1, d1, d0] concat: d0 block comes first -> d0 wins ties
            result[j] = (v0 <= v1) ? i0 : (MCW + i1);
        }
    }
    __syncthreads();
    if (t < 128) {
        const int j = t >> 5, bit = t & 31;
        out[(q0 + j) * 32 + bit] = (float)((result[j] >> bit) & 1);
    }
}

// ---------------- launch ----------------
extern "C" void kernel_launch(void* const* d_in, const int* in_sizes, int n_in,
                              void* d_out, int out_size) {
    // Identify inputs by element count, NOT by position:
    //   x    : 64*2*126*128   = 2,064,384
    //   data : 16001*2*126*8  = 32,258,016
    const void* x    = d_in[0];
    const void* data = d_in[1];
    if (n_in >= 2 && in_sizes[0] > in_sizes[1]) {
        x    = d_in[1];
        data = d_in[0];
    }
    float* out = (float*)d_out;   // [64,512], float 0.0/1.0

    detect_kernel<<<1, 1>>>((const uint32_t*)x, (const uint32_t*)data);
    build_xq_kernel<<<NQ, 256>>>(x);
    prep_cb_kernel<<<MCW, 128>>>(data);
    gemm_kernel<<<dim3(MPAD / BN, NQ / BM), 512>>>();
    argmin_kernel<<<NQ / 4, 256>>>(out);
}

// round 14
// speedup vs baseline: 1.4331x; 1.4331x over previous
#include <cuda_runtime.h>
#include <cuda_fp16.h>
#include <cuda_bf16.h>
#include <cstdint>

// ---------------- problem constants ----------------
#define NQ      1024      // 64 batches * 16 slots
#define MCW     16001     // codebook rows
#define MPAD    16128     // 126 * 128
#define KDIM    2016
#define BM      64        // q rows per CTA
#define BN      64        // m cols per CTA
#define BK      32        // halfs per k stage
#define NKITER  63        // 2016 / 32
#define SEGLEN  3         // k-iters per accumulation segment (63 = 21*3)

// dtype codes
#define DT_F16  0
#define DT_BF16 1
#define DT_F32  2

// ---------------- scratch (static device memory; no allocs) ----------------
__device__ int    g_dt_x;
__device__ int    g_dt_d;
__device__ __half g_xq[NQ * KDIM];           // permuted queries, k-major
__device__ __half g_cb[(size_t)MPAD * KDIM]; // codebook fp16 (rows >= MCW stay zero)
__device__ float  g_xs[NQ];
__device__ float  g_x2[NQ];
__device__ float  g_c2[MPAD];
__device__ float  g_cn2[MPAD];
__device__ unsigned long long g_m0[NQ];      // packed (key(d0)<<32 | idx) running min
__device__ unsigned long long g_m1[NQ];      // packed (key(d1)<<32 | idx) running min

// ---------------- small PTX helpers ----------------
__device__ __forceinline__ uint32_t smem_u32(const void* p) {
    uint32_t a;
    asm("{ .reg .u64 t; cvta.to.shared.u64 t, %1; cvt.u32.u64 %0, t; }" : "=r"(a) : "l"(p));
    return a;
}
__device__ __forceinline__ void cp16(uint32_t dst, const void* src) {
    asm volatile("cp.async.cg.shared.global [%0], [%1], 16;\n" :: "r"(dst), "l"(src));
}
__device__ __forceinline__ void cp_commit() { asm volatile("cp.async.commit_group;\n"); }
__device__ __forceinline__ void ldsm4(uint32_t* r, uint32_t addr) {
    asm volatile("ldmatrix.sync.aligned.m8n8.x4.shared.b16 {%0,%1,%2,%3}, [%4];"
                 : "=r"(r[0]), "=r"(r[1]), "=r"(r[2]), "=r"(r[3]) : "r"(addr));
}
__device__ __forceinline__ void mma16816(float* d, const uint32_t* a, uint32_t b0, uint32_t b1) {
    asm volatile("mma.sync.aligned.m16n8k16.row.col.f32.f16.f16.f32 "
                 "{%0,%1,%2,%3}, {%4,%5,%6,%7}, {%8,%9}, {%0,%1,%2,%3};\n"
                 : "+f"(d[0]), "+f"(d[1]), "+f"(d[2]), "+f"(d[3])
                 : "r"(a[0]), "r"(a[1]), "r"(a[2]), "r"(a[3]), "r"(b0), "r"(b1));
}
// order-preserving float->u32 key (monotone for all floats incl. negatives)
__device__ __forceinline__ uint32_t fkey(float f) {
    uint32_t b = __float_as_uint(f);
    return (b & 0x80000000u) ? ~b : (b | 0x80000000u);
}

// ---------------- generic 8-element load ----------------
__device__ __forceinline__ void load8(const void* p, size_t off, int dt, float* f) {
    if (dt == DT_F32) {
        const float4* q = (const float4*)((const float*)p + off);
        float4 v0 = q[0], v1 = q[1];
        f[0]=v0.x; f[1]=v0.y; f[2]=v0.z; f[3]=v0.w;
        f[4]=v1.x; f[5]=v1.y; f[6]=v1.z; f[7]=v1.w;
    } else if (dt == DT_F16) {
        uint4 v = *(const uint4*)((const __half*)p + off);
        const __half2* hp = (const __half2*)&v;
#pragma unroll
        for (int i = 0; i < 4; i++) {
            float2 g = __half22float2(hp[i]);
            f[2*i] = g.x; f[2*i+1] = g.y;
        }
    } else {
        uint4 v = *(const uint4*)((const __nv_bfloat16*)p + off);
        const __nv_bfloat162* hp = (const __nv_bfloat162*)&v;
#pragma unroll
        for (int i = 0; i < 4; i++) {
            float2 g = __bfloat1622float2(hp[i]);
            f[2*i] = g.x; f[2*i+1] = g.y;
        }
    }
}

// ---------------- kernel 0: dtype detection ----------------
__global__ void detect_kernel(const uint32_t* x, const uint32_t* d) {
    const uint32_t* ps[2] = {x, d};
    int* outs[2] = {&g_dt_x, &g_dt_d};
    for (int a = 0; a < 2; a++) {
        uint32_t lowmax = 0, highmax = 0;
        for (int i = 0; i < 64; i++) {
            uint32_t w = ps[a][i];
            uint32_t lo = w & 0xFFFFu, hi = w >> 16;
            if (lo > lowmax) lowmax = lo;
            if (hi > highmax) highmax = hi;
        }
        int dt;
        if (lowmax >= 0x4000u)       dt = DT_F32;
        else if (highmax >= 0x3C00u) dt = DT_BF16;
        else                         dt = DT_F16;
        *outs[a] = dt;
    }
}

// ---------------- kernel 0b: reset packed mins (every launch) ----------------
__global__ void init_min_kernel() {
    const int i = blockIdx.x * blockDim.x + threadIdx.x;
    if (i < NQ) { g_m0[i] = ~0ull; g_m1[i] = ~0ull; }
}

// ---------------- kernel 1: permute x -> xq (fp16), compute xs/x2 ----------------
__global__ __launch_bounds__(256) void build_xq_kernel(const void* xraw) {
    const int q = blockIdx.x;
    const int b = q >> 4, slot = q & 15;
    const int t = threadIdx.x;
    const int dt = g_dt_x;
    float s = 0.f, s2 = 0.f;
    if (t < 252) {
        const int ch = t / 126, row = t % 126;
        const size_t off = (size_t)b * 32256 + ch * 16128 + row * 128 + slot * 8;
        float f[8];
        load8(xraw, off, dt, f);
        __half h[8];
#pragma unroll
        for (int i = 0; i < 8; i++) {
            h[i] = __float2half_rn(f[i]);
            s  += f[i];
            s2 += f[i] * f[i];
        }
        *(uint4*)(g_xq + (size_t)q * KDIM + t * 8) = *(const uint4*)h;
    }
    __shared__ float r0[256], r1[256];
    r0[t] = s; r1[t] = s2; __syncthreads();
    for (int st = 128; st > 0; st >>= 1) {
        if (t < st) { r0[t] += r0[t + st]; r1[t] += r1[t + st]; }
        __syncthreads();
    }
    if (t == 0) { g_xs[q] = r0[0]; g_x2[q] = r1[0]; }
}

// ---------------- kernel 2: codebook -> fp16 + per-row c2/cn2 ----------------
__global__ __launch_bounds__(128) void prep_cb_kernel(const void* draw) {
    const int m = blockIdx.x;
    const int t = threadIdx.x;
    const int dt = g_dt_d;
    __half* dst = g_cb + (size_t)m * KDIM;
    float s2 = 0.f, sn2 = 0.f;
    for (int v = t; v < 252; v += 128) {
        float f[8];
        load8(draw, (size_t)m * KDIM + v * 8, dt, f);
        __half h[8];
#pragma unroll
        for (int i = 0; i < 8; i++) {
            h[i] = __float2half_rn(f[i]);
            s2 += f[i] * f[i];
            float g1 = 1.0f - f[i];
            sn2 += g1 * g1;
        }
        *(uint4*)(dst + v * 8) = *(const uint4*)h;
    }
    __shared__ float r0[128], r1[128];
    r0[t] = s2; r1[t] = sn2; __syncthreads();
    for (int st = 64; st > 0; st >>= 1) {
        if (t < st) { r0[t] += r0[t + st]; r1[t] += r1[t + st]; }
        __syncthreads();
    }
    if (t == 0) { g_c2[m] = r0[0]; g_cn2[m] = r1[0]; }
}

// ---------------- kernel 3: GEMM + fused distance/argmin ----------------
// CTA tile 64q x 64m, 256 threads / 8 warps (warp tile 32q x 16m), 3-stage
// cp.async pipeline with ONE barrier per k-iter, targeting 3 CTAs/SM.
// Numerics identical to the R6/R11 passes: per-3-iter MMA segments Kahan-folded
// with __fadd_rn/__fsub_rn. Epilogue computes d0/d1 from in-register xc (same
// op order as the passing argmin kernel) and min-reduces packed (key|index)
// u64s: smem atomicMin_block, then one global atomicMin per (q,dist) per CTA.
// Packed index => first-occurrence tie-break, exactly like the reference.
#define APITCH 40
#define A_STAGE (BM * APITCH)             // 2560 halfs
#define B_STAGE (BN * APITCH)
#define A_STAGE_BYTES (A_STAGE * 2)       // 5120 B
#define B_STAGE_BYTES (B_STAGE * 2)

__global__ __launch_bounds__(256, 3) void gemm_kernel() {
    __shared__ __half sA[3][A_STAGE];
    __shared__ __half sB[3][B_STAGE];
    __shared__ unsigned long long s_min0[BM];
    __shared__ unsigned long long s_min1[BM];

    const int tile_m = blockIdx.x * BM;    // q tile (x fastest: 16 q-tiles share cb rows in L2)
    const int tile_n = blockIdx.y * BN;    // m tile
    const int tid  = threadIdx.x;
    const int wid  = tid >> 5;
    const int lane = tid & 31;
    const int warp_q = wid & 1;    // 2 q-groups of 32
    const int warp_n = wid >> 1;   // 4 n-groups of 16

    const uint32_t sA_u = smem_u32(&sA[0][0]);
    const uint32_t sB_u = smem_u32(&sB[0][0]);

    // global-load mapping: thread -> one A cp16 + one B cp16 per stage
    const int rowL = tid >> 2;             // 0..63
    const int ka   = (tid & 3) * 8;
    const __half* gA = g_xq + (size_t)(tile_m + rowL) * KDIM + ka;
    const __half* gB = g_cb + (size_t)(tile_n + rowL) * KDIM + ka;
    const uint32_t dA = sA_u + ((rowL * APITCH + ka) << 1);
    const uint32_t dB = sB_u + ((rowL * APITCH + ka) << 1);

    float sum[2][2][4], comp[2][2][4], chunk[2][2][4];
#pragma unroll
    for (int i = 0; i < 2; i++)
#pragma unroll
        for (int j = 0; j < 2; j++)
#pragma unroll
            for (int k = 0; k < 4; k++) { sum[i][j][k] = 0.f; comp[i][j][k] = 0.f; chunk[i][j][k] = 0.f; }

    // ldmatrix per-lane addressing (same scheme as the R6 pass)
    const int arow  = warp_q * 32 + (lane & 15);
    const int akoff = (lane >> 4) << 3;
    const int bn    = warp_n * 16 + (lane & 7) + ((lane >> 4) << 3);
    const int bkoff = lane & 8;

    // prologue: stages 0, 1
#pragma unroll
    for (int s = 0; s < 2; s++) {
        const int k0 = s * BK;
        cp16(dA + s * A_STAGE_BYTES, gA + k0);
        cp16(dB + s * B_STAGE_BYTES, gB + k0);
        cp_commit();
    }

    for (int kt = 0; kt < NKITER; kt++) {
        // pending before this wait: G_kt, G_{kt+1} (none newer issued yet);
        // at kt==62 only G_62 is pending -> drain all.
        if (kt < NKITER - 1) asm volatile("cp.async.wait_group 1;\n");
        else                 asm volatile("cp.async.wait_group 0;\n");
        __syncthreads();   // also protects buffer (kt+2)%3 (consumed at kt-1) for reuse

        // issue loads for stage kt+2 into the freed buffer, then compute
        if (kt + 2 < NKITER) {
            const int nbuf = (kt + 2) % 3;
            const int k0 = (kt + 2) * BK;
            cp16(dA + nbuf * A_STAGE_BYTES, gA + k0);
            cp16(dB + nbuf * B_STAGE_BYTES, gB + k0);
            cp_commit();
        }

        const int buf = kt % 3;
        const uint32_t aB = sA_u + buf * A_STAGE_BYTES;
        const uint32_t bB = sB_u + buf * B_STAGE_BYTES;
#pragma unroll
        for (int ks = 0; ks < 2; ks++) {
            const int kh = ks * 16;
            uint32_t ra[2][4], rb[4];
            uint32_t a0 = aB + ((arow * APITCH + kh + akoff) << 1);
            ldsm4(ra[0], a0);
            ldsm4(ra[1], a0 + (16 * APITCH << 1));
            ldsm4(rb, bB + ((bn * APITCH + kh + bkoff) << 1));
#pragma unroll
            for (int mt = 0; mt < 2; mt++)
#pragma unroll
                for (int nt = 0; nt < 2; nt++)
                    mma16816(chunk[mt][nt], ra[mt], rb[nt * 2], rb[nt * 2 + 1]);
        }

        if ((kt % SEGLEN) == (SEGLEN - 1)) {
#pragma unroll
            for (int mt = 0; mt < 2; mt++)
#pragma unroll
                for (int nt = 0; nt < 2; nt++)
#pragma unroll
                    for (int e = 0; e < 4; e++) {
                        float y = __fsub_rn(chunk[mt][nt][e], comp[mt][nt][e]);
                        float tt = __fadd_rn(sum[mt][nt][e], y);
                        comp[mt][nt][e] = __fsub_rn(__fsub_rn(tt, sum[mt][nt][e]), y);
                        sum[mt][nt][e] = tt;
                        chunk[mt][nt][e] = 0.f;
                    }
        }
    }

    // -------- fused epilogue: distances + packed argmin --------
    for (int i = tid; i < BM; i += 256) { s_min0[i] = ~0ull; s_min1[i] = ~0ull; }
    __syncthreads();

    // per-thread m columns (4) and q rows (4)
    int   gm[2][2]; float vc2[2][2], vcn2[2][2]; bool mok[2][2];
#pragma unroll
    for (int nt = 0; nt < 2; nt++)
#pragma unroll
        for (int e1 = 0; e1 < 2; e1++) {
            int m = tile_n + warp_n * 16 + nt * 8 + (lane & 3) * 2 + e1;
            gm[nt][e1] = m;
            mok[nt][e1] = (m < MCW);
            vc2[nt][e1]  = mok[nt][e1] ? g_c2[m]  : 0.f;
            vcn2[nt][e1] = mok[nt][e1] ? g_cn2[m] : 0.f;
        }

#pragma unroll
    for (int mt = 0; mt < 2; mt++)
#pragma unroll
        for (int e2 = 0; e2 < 2; e2++) {
            const int qloc = warp_q * 32 + mt * 16 + (lane >> 2) + e2 * 8;
            const float x2v = g_x2[tile_m + qloc];
            const float xsv = g_xs[tile_m + qloc];
            unsigned long long b0 = ~0ull, b1 = ~0ull;
#pragma unroll
            for (int nt = 0; nt < 2; nt++)
#pragma unroll
                for (int e1 = 0; e1 < 2; e1++) {
                    if (!mok[nt][e1]) continue;
                    const int e = e2 * 2 + e1;
                    const float xc = __fadd_rn(sum[mt][nt][e], comp[mt][nt][e]);
                    const float d0 = __fsub_rn(__fadd_rn(x2v, vc2[nt][e1]), 2.0f * xc);
                    const float d1 = __fsub_rn(__fadd_rn(x2v, vcn2[nt][e1]),
                                               2.0f * __fsub_rn(xsv, xc));
                    unsigned long long p0 = ((unsigned long long)fkey(d0) << 32) | (uint32_t)gm[nt][e1];
                    unsigned long long p1 = ((unsigned long long)fkey(d1) << 32) | (uint32_t)gm[nt][e1];
                    if (p0 < b0) b0 = p0;
                    if (p1 < b1) b1 = p1;
                }
            atomicMin_block(&s_min0[qloc], b0);
            atomicMin_block(&s_min1[qloc], b1);
        }
    __syncthreads();

    if (tid < BM) {
        atomicMin(&g_m0[tile_m + tid], s_min0[tid]);
        atomicMin(&g_m1[tile_m + tid], s_min1[tid]);
    }
}

// ---------------- kernel 4: finalize -> bits ----------------
__global__ void finalize_kernel(float* __restrict__ out) {
    const int q = blockIdx.x * blockDim.x + threadIdx.x;
    if (q >= NQ) return;
    const unsigned long long v0 = g_m0[q];
    const unsigned long long v1 = g_m1[q];
    const uint32_t k0 = (uint32_t)(v0 >> 32);
    const uint32_t k1 = (uint32_t)(v1 >> 32);
    // [d0, d1, d1, d0] concat: d0 block first -> d0 wins ties
    const int res = (k0 <= k1) ? (int)(v0 & 0xFFFFFFFFu) : MCW + (int)(v1 & 0xFFFFFFFFu);
#pragma unroll
    for (int b = 0; b < 32; b++)
        out[q * 32 + b] = (float)((res >> b) & 1);
}

// ---------------- launch ----------------
extern "C" void kernel_launch(void* const* d_in, const int* in_sizes, int n_in,
                              void* d_out, int out_size) {
    // Identify inputs by element count, NOT by position:
    //   x    : 64*2*126*128   = 2,064,384
    //   data : 16001*2*126*8  = 32,258,016
    const void* x    = d_in[0];
    const void* data = d_in[1];
    if (n_in >= 2 && in_sizes[0] > in_sizes[1]) {
        x    = d_in[1];
        data = d_in[0];
    }
    float* out = (float*)d_out;   // [64,512], float 0.0/1.0

    detect_kernel<<<1, 1>>>((const uint32_t*)x, (const uint32_t*)data);
    init_min_kernel<<<4, 256>>>();
    build_xq_kernel<<<NQ, 256>>>(x);
    prep_cb_kernel<<<MCW, 128>>>(data);
    gemm_kernel<<<dim3(NQ / BM, MPAD / BN), 256>>>();
    finalize_kernel<<<4, 256>>>(out);
}